// round 6
// baseline (speedup 1.0000x reference)
#include <cuda_runtime.h>
#include <cuda_bf16.h>
#include <cstdint>

// InverseAvgPool1d, K=8 -> half=4, s=9.
// out[t] = 8*(A[t] - A[t-1]) + 8*x0*( [t%9==5] - [t%9==0] ),
// where A[t] = stride-9 prefix sum of x along the row, A[-1]=0.
//
// Persistent grid-stride CTAs (grid = 6*148, all resident), double-buffered
// smem; next row prefetched with cp.async.cg (LDGSTS) overlapping compute.

#define ROW_T 4096
#define NWARP 9
#define NTHREADS (NWARP * 32)   // 288
#define PER_LANE 15             // 32*15 = 480 slots; real max 456
#define GRID_PERSIST (6 * 148)  // 888

__device__ __forceinline__ void cp16(uint32_t smem_dst, const void* gsrc) {
    asm volatile("cp.async.cg.shared.global [%0], [%1], 16;"
                 :: "r"(smem_dst), "l"(gsrc) : "memory");
}

__global__ __launch_bounds__(NTHREADS, 6)
void inv_avgpool_kernel(const float* __restrict__ x, float* __restrict__ out,
                        int rows) {
    __shared__ __align__(16) float sbuf[2][ROW_T];

    const int tid = threadIdx.x;
    const int lane = tid & 31;
    const int r = tid >> 5;                  // residue chain 0..8

    const uint32_t sb[2] = {
        (uint32_t)__cvta_generic_to_shared(&sbuf[0][0]),
        (uint32_t)__cvta_generic_to_shared(&sbuf[1][0])
    };

    const int n = (r == 0) ? 456 : 455;      // chain length
    const int base = r + 135 * lane;         // lanes 0..29: base+126 <= 4049
    const int lim30 = n - 450;               // valid count for lane 30 (5 or 6)

    // residue-correction coefficients for the diff pass (static per thread)
    const int rr0 = (4 * tid) % 9;
    const int rr1 = (rr0 + 1) % 9, rr2 = (rr0 + 2) % 9, rr3 = (rr0 + 3) % 9;
    const float cfx = (rr0 == 5) ? 8.f : (rr0 == 0) ? -8.f : 0.f;
    const float cfy = (rr1 == 5) ? 8.f : (rr1 == 0) ? -8.f : 0.f;
    const float cfz = (rr2 == 5) ? 8.f : (rr2 == 0) ? -8.f : 0.f;
    const float cfw = (rr3 == 5) ? 8.f : (rr3 == 0) ? -8.f : 0.f;

    // prologue: prefetch first row into buffer 0
    {
        const float* xr = x + (size_t)blockIdx.x * ROW_T;
        for (int q = tid; q < ROW_T / 4; q += NTHREADS)
            cp16(sb[0] + 16u * q, xr + 4 * q);
        asm volatile("cp.async.commit_group;" ::: "memory");
    }

    int cur = 0;
    for (int row = blockIdx.x; row < rows; row += GRID_PERSIST) {
        float* s = sbuf[cur];

        // wait for current buffer; barrier also closes last iter's reads of buf^1
        asm volatile("cp.async.wait_group 0;" ::: "memory");
        __syncthreads();

        // prefetch next row into the other buffer (free since 2 iters ago)
        const int nxt = row + GRID_PERSIST;
        if (nxt < rows) {
            const float* xr = x + (size_t)nxt * ROW_T;
            const uint32_t dst = sb[cur ^ 1];
            for (int q = tid; q < ROW_T / 4; q += NTHREADS)
                cp16(dst + 16u * q, xr + 4 * q);
        }
        asm volatile("cp.async.commit_group;" ::: "memory");

        const float x0 = s[0];

        // gather: lane l serially accumulates chain slots [15l,15l+15)
        float a[PER_LANE];
        float run = 0.f;
        if (lane < 30) {
            #pragma unroll
            for (int j = 0; j < PER_LANE; j++) { run += s[base + 9 * j]; a[j] = run; }
        } else if (lane == 30) {
            #pragma unroll
            for (int j = 0; j < PER_LANE; j++) {
                if (j < lim30) run += s[base + 9 * j];
                a[j] = run;
            }
        }
        __syncthreads();

        // warp scan over lane totals -> exclusive carry
        float incl = run;
        #pragma unroll
        for (int off = 1; off < 32; off <<= 1) {
            float up = __shfl_up_sync(0xffffffffu, incl, off);
            if (lane >= off) incl += up;
        }
        const float e8 = 8.f * (incl - run);

        // writeback 8*A in place
        if (lane < 30) {
            #pragma unroll
            for (int j = 0; j < PER_LANE; j++) s[base + 9 * j] = fmaf(8.f, a[j], e8);
        } else if (lane == 30) {
            #pragma unroll
            for (int j = 0; j < PER_LANE; j++)
                if (j < lim30) s[base + 9 * j] = fmaf(8.f, a[j], e8);
        }
        __syncthreads();

        // diff pass: out[t] = 8A[t]-8A[t-1] + cf*x0
        float4* __restrict__ outr = (float4*)(out + (size_t)row * ROW_T);
        #pragma unroll
        for (int q = tid; q < ROW_T / 4; q += NTHREADS) {
            float4 B = ((const float4*)s)[q];
            float prevw = __shfl_up_sync(0xffffffffu, B.w, 1);
            if (lane == 0) prevw = (q == 0) ? 0.f : s[4 * q - 1];
            float4 o;
            o.x = (B.x - prevw) + cfx * x0;
            o.y = (B.y - B.x) + cfy * x0;
            o.z = (B.z - B.y) + cfz * x0;
            o.w = (B.w - B.z) + cfw * x0;
            outr[q] = o;
        }

        cur ^= 1;
    }
}

extern "C" void kernel_launch(void* const* d_in, const int* in_sizes, int n_in,
                              void* d_out, int out_size) {
    const float* x = (const float*)d_in[0];
    float* out = (float*)d_out;
    const int rows = in_sizes[0] / ROW_T;       // 16384
    inv_avgpool_kernel<<<GRID_PERSIST, NTHREADS>>>(x, out, rows);
}